// round 4
// baseline (speedup 1.0000x reference)
#include <cuda_runtime.h>
#include <math.h>

#define BB    16
#define TT    3300
#define FEAT  80
#define NC    512
#define RNN   512
#define G3    1536
#define DIN   592
#define NBLK  128   // persistent GRU blocks

// ---------------- device scratch (no allocation allowed) ----------------
__device__ float    g_melsup[(size_t)BB * TT * FEAT];     // [b][t][f]
__device__ float    g_wohT[(size_t)NC * G3];              // [class][gate-row]
__device__ float    g_xproj[(size_t)TT * G3 * BB];        // [t][row][b] (includes b_ih)
__device__ float    g_hs[(size_t)BB * TT * RNN];          // GRU outputs
__device__ float    g_h1[(size_t)BB * TT * RNN];          // fc1 output
__device__ float    g_hbuf[2][BB * RNN];                  // ping-pong hidden state
__device__ unsigned g_cnt;                                // barrier counter

__device__ __forceinline__ float sigm(float x) { return 1.f / (1.f + __expf(-x)); }

// ---------------- init ----------------
__global__ void k_init() {
    int i = blockIdx.x * 256 + threadIdx.x;
    if (i < 2 * BB * RNN) ((float*)g_hbuf)[i] = 0.f;
    if (i == 0) g_cnt = 0u;
}

// ---------------- transpose one-hot table: wohT[c][g] = w_ih[g][c] ----------------
__global__ void k_woh(const float* __restrict__ w_ih) {
    int idx = blockIdx.x * 256 + threadIdx.x;          // 512*1536 total
    if (idx >= NC * G3) return;
    int g = idx % G3, c = idx / G3;
    g_wohT[(size_t)c * G3 + g] = __ldg(&w_ih[(size_t)g * DIN + c]);
}

// ---------------- mel upsample: one block per (b,f) ----------------
__global__ void k_upsample(const float* __restrict__ mels,
                           const float* __restrict__ k0,
                           const float* __restrict__ k1,
                           const float* __restrict__ k2) {
    int bf = blockIdx.x;
    int b = bf / FEAT, f = bf % FEAT;
    __shared__ float s0[16], s1[80], s2[400], c0[11], c1[11], c2[23];
    int tid = threadIdx.x;
    if (tid < 16) s0[tid] = mels[((size_t)b * FEAT + f) * 16 + tid];
    if (tid < 11) c0[tid] = k0[tid];
    if (tid < 11) c1[tid] = k1[tid];
    if (tid < 23) c2[tid] = k2[tid];
    __syncthreads();
    if (tid < 80) {
        float a = 0.f;
        #pragma unroll
        for (int u = 0; u < 11; u++) {
            int p = tid + u - 5;
            if (p >= 0 && p < 80) a += c0[u] * s0[p / 5];
        }
        s1[tid] = a;
    }
    __syncthreads();
    if (tid < 400) {
        float a = 0.f;
        #pragma unroll
        for (int u = 0; u < 11; u++) {
            int p = tid + u - 5;
            if (p >= 0 && p < 400) a += c1[u] * s1[p / 5];
        }
        s2[tid] = a;
    }
    __syncthreads();
    for (int i = tid; i < TT; i += blockDim.x) {
        int p = i + 550;                                  // crop indent
        float a = 0.f;
        #pragma unroll
        for (int u = 0; u < 23; u++) a += c2[u] * s2[(p + u - 11) / 11];  // always in [539,3860]
        g_melsup[((size_t)b * TT + i) * FEAT + f] = a;
    }
}

// ---------------- x_proj precompute: one block per t ----------------
// xp[t][row][b] = wohT[x[b][t]][row] + b_ih[row] + sum_f mel[b][t][f]*w_ih[row][512+f]
__global__ void __launch_bounds__(256) k_xproj(const int* __restrict__ x,
                                               const float* __restrict__ w_ih,
                                               const float* __restrict__ b_ih) {
    int t = blockIdx.x;
    int tid = threadIdx.x;
    __shared__ float mel_s[BB][FEAT];      // [b][f]
    __shared__ int   cls_s[BB];
    for (int i = tid; i < BB * FEAT; i += 256) {
        int b = i / FEAT, f = i % FEAT;
        mel_s[b][f] = g_melsup[((size_t)b * TT + t) * FEAT + f];
    }
    if (tid < BB) cls_s[tid] = x[(size_t)tid * TT + t];
    __syncthreads();

    for (int r = tid; r < G3; r += 256) {
        float acc[BB];
        float bi = b_ih[r];
        #pragma unroll
        for (int b = 0; b < BB; b++)
            acc[b] = bi + g_wohT[(size_t)cls_s[b] * G3 + r];
        const float* wrow = &w_ih[(size_t)r * DIN + NC];   // mel part, 16B aligned
        #pragma unroll 4
        for (int fq = 0; fq < FEAT / 4; fq++) {
            float4 w4 = __ldg((const float4*)wrow + fq);
            #pragma unroll
            for (int b = 0; b < BB; b++) {
                float4 m4 = *(const float4*)&mel_s[b][4 * fq];
                acc[b] += w4.x * m4.x + w4.y * m4.y + w4.z * m4.z + w4.w * m4.w;
            }
        }
        float* dst = &g_xproj[((size_t)t * G3 + r) * BB];
        #pragma unroll
        for (int q = 0; q < 4; q++)
            *(float4*)&dst[4 * q] = make_float4(acc[4*q], acc[4*q+1], acc[4*q+2], acc[4*q+3]);
    }
}

// ---------------- persistent GRU kernel ----------------
__global__ void __launch_bounds__(256, 1) k_gru(const float* __restrict__ w_hh,
                                                const float* __restrict__ b_hh) {
    int bk = blockIdx.x;
    int j0 = bk * 4;                      // 4 hidden units per block
    int tid = threadIdx.x;
    int wi = tid >> 5, lane = tid & 31;
    int rg = wi & 3;                      // rowgroup: 3 local rows each
    int bh = wi >> 2;                     // batch half: 8 batches each

    // register-resident weights: 3 rows x 16 floats/lane
    float w[3][16];
    float bhh[3];
    #pragma unroll
    for (int q = 0; q < 3; q++) {
        int lr = rg * 3 + q;              // local row 0..11 == g*4+u
        int g = lr >> 2, u = lr & 3;
        int row = g * RNN + j0 + u;
        bhh[q] = b_hh[row];
        #pragma unroll
        for (int i = 0; i < 4; i++) {
            float4 v = *(const float4*)&w_hh[(size_t)row * RNN + i * 128 + 4 * lane];
            w[q][4*i] = v.x; w[q][4*i+1] = v.y; w[q][4*i+2] = v.z; w[q][4*i+3] = v.w;
        }
    }

    __shared__ float h_s[BB][RNN];        // 32 KB
    __shared__ float y_s[12][BB];
    __shared__ float xp_s[12][BB];

    int cur = 0;
    for (int t = 0; t < TT; t++) {
        if (tid < 192) {                  // stage x_proj for this block's 12 rows
            int lr = tid >> 4, b = tid & 15;
            int g = lr >> 2, u = lr & 3;
            int row = g * RNN + j0 + u;
            xp_s[lr][b] = g_xproj[((size_t)t * G3 + row) * BB + b];
        }
        {                                 // stage h (bypass L1: written by other SMs)
            const float4* src = (const float4*)g_hbuf[cur];
            float4* dst = (float4*)&h_s[0][0];
            #pragma unroll
            for (int i = 0; i < 8; i++) dst[tid + 256 * i] = __ldcg(src + tid + 256 * i);
        }
        __syncthreads();

        // 12 rows x 16 batches warp-collective dots
        #pragma unroll 2
        for (int bi = 0; bi < 8; bi++) {
            int b = bh * 8 + bi;
            float4 h0 = *(const float4*)&h_s[b][4 * lane];
            float4 h1 = *(const float4*)&h_s[b][128 + 4 * lane];
            float4 h2 = *(const float4*)&h_s[b][256 + 4 * lane];
            float4 h3 = *(const float4*)&h_s[b][384 + 4 * lane];
            #pragma unroll
            for (int q = 0; q < 3; q++) {
                float a;
                a  = w[q][0]*h0.x + w[q][1]*h0.y + w[q][2]*h0.z + w[q][3]*h0.w;
                a += w[q][4]*h1.x + w[q][5]*h1.y + w[q][6]*h1.z + w[q][7]*h1.w;
                a += w[q][8]*h2.x + w[q][9]*h2.y + w[q][10]*h2.z + w[q][11]*h2.w;
                a += w[q][12]*h3.x + w[q][13]*h3.y + w[q][14]*h3.z + w[q][15]*h3.w;
                #pragma unroll
                for (int off = 16; off; off >>= 1) a += __shfl_xor_sync(0xffffffffu, a, off);
                if (lane == 0) y_s[rg * 3 + q][b] = a + bhh[q];
            }
        }
        __syncthreads();

        int nxt = cur ^ 1;
        if (tid < 64) {                   // gate epilogue: 4 units x 16 batches
            int u = tid >> 4, b = tid & 15;
            float r = sigm(xp_s[u][b]     + y_s[u][b]);
            float z = sigm(xp_s[4 + u][b] + y_s[4 + u][b]);
            float n = tanhf(xp_s[8 + u][b] + r * y_s[8 + u][b]);
            float hv = (1.f - z) * n + z * h_s[b][j0 + u];
            int j = j0 + u;
            __stcg(&g_hbuf[nxt][b * RNN + j], hv);
            g_hs[((size_t)b * TT + t) * RNN + j] = hv;
            __threadfence();
        }
        __syncthreads();
        if (tid == 0) {                   // grid barrier (monotone counter)
            unsigned tgt = (unsigned)(t + 1) * (unsigned)NBLK;
            atomicAdd(&g_cnt, 1u);
            while (*(volatile unsigned*)&g_cnt < tgt) { }
        }
        __syncthreads();
        cur = nxt;
    }
}

// ---------------- tiled fp32 GEMM: C[m][n] = act(A[m][:]·W[n][:] + bias[n]) ----------------
// M x 512 x 512, BM=BN=64, BK=16, 256 threads, 4x4 per thread
template<int ACT>
__global__ void __launch_bounds__(256) k_gemm(const float* __restrict__ A,
                                              const float* __restrict__ W,
                                              const float* __restrict__ bias,
                                              float* __restrict__ C) {
    __shared__ float As[16][68];
    __shared__ float Bs[16][68];
    int m0 = blockIdx.x * 64, n0 = blockIdx.y * 64;
    int tid = threadIdx.x;
    int tm = tid & 15, tn = tid >> 4;
    int lr = tid >> 2, lq = tid & 3;
    float acc[4][4] = {};

    for (int k0 = 0; k0 < 512; k0 += 16) {
        float4 av = *(const float4*)&A[(size_t)(m0 + lr) * 512 + k0 + 4 * lq];
        float4 bv = *(const float4*)&W[(size_t)(n0 + lr) * 512 + k0 + 4 * lq];
        __syncthreads();
        As[4*lq+0][lr] = av.x; As[4*lq+1][lr] = av.y; As[4*lq+2][lr] = av.z; As[4*lq+3][lr] = av.w;
        Bs[4*lq+0][lr] = bv.x; Bs[4*lq+1][lr] = bv.y; Bs[4*lq+2][lr] = bv.z; Bs[4*lq+3][lr] = bv.w;
        __syncthreads();
        #pragma unroll
        for (int k = 0; k < 16; k++) {
            float4 a = *(const float4*)&As[k][4 * tm];
            float4 b = *(const float4*)&Bs[k][4 * tn];
            acc[0][0] += a.x*b.x; acc[0][1] += a.x*b.y; acc[0][2] += a.x*b.z; acc[0][3] += a.x*b.w;
            acc[1][0] += a.y*b.x; acc[1][1] += a.y*b.y; acc[1][2] += a.y*b.z; acc[1][3] += a.y*b.w;
            acc[2][0] += a.z*b.x; acc[2][1] += a.z*b.y; acc[2][2] += a.z*b.z; acc[2][3] += a.z*b.w;
            acc[3][0] += a.w*b.x; acc[3][1] += a.w*b.y; acc[3][2] += a.w*b.z; acc[3][3] += a.w*b.w;
        }
    }
    #pragma unroll
    for (int i = 0; i < 4; i++) {
        int m = m0 + 4 * tm + i;
        #pragma unroll
        for (int j = 0; j < 4; j++) {
            int n = n0 + 4 * tn + j;
            float v = acc[i][j] + bias[n];
            if (ACT == 1) v = fmaxf(v, 0.f);
            C[(size_t)m * 512 + n] = v;
        }
    }
}

// ---------------- launch ----------------
extern "C" void kernel_launch(void* const* d_in, const int* in_sizes, int n_in,
                              void* d_out, int out_size) {
    const int*   x     = (const int*)  d_in[0];
    const float* mels  = (const float*)d_in[1];
    const float* up_k0 = (const float*)d_in[2];
    const float* up_k1 = (const float*)d_in[3];
    const float* up_k2 = (const float*)d_in[4];
    const float* w_ih  = (const float*)d_in[5];
    const float* w_hh  = (const float*)d_in[6];
    const float* b_ih  = (const float*)d_in[7];
    const float* b_hh  = (const float*)d_in[8];
    const float* fc1_w = (const float*)d_in[9];
    const float* fc1_b = (const float*)d_in[10];
    const float* fc2_w = (const float*)d_in[11];
    const float* fc2_b = (const float*)d_in[12];
    float* out = (float*)d_out;

    float *d_hs, *d_h1;
    cudaGetSymbolAddress((void**)&d_hs, g_hs);
    cudaGetSymbolAddress((void**)&d_h1, g_h1);

    k_init<<<64, 256>>>();
    k_woh<<<(NC * G3 + 255) / 256, 256>>>(w_ih);
    k_upsample<<<BB * FEAT, 512>>>(mels, up_k0, up_k1, up_k2);
    k_xproj<<<TT, 256>>>(x, w_ih, b_ih);
    k_gru<<<NBLK, 256>>>(w_hh, b_hh);

    dim3 gg(BB * TT / 64, 512 / 64);
    k_gemm<1><<<gg, 256>>>(d_hs, fc1_w, fc1_b, d_h1);
    k_gemm<0><<<gg, 256>>>(d_h1, fc2_w, fc2_b, out);
}